// round 9
// baseline (speedup 1.0000x reference)
#include <cuda_runtime.h>
#include <math.h>

// Problem constants
#define Nn 32768
#define Dd 512
#define Kk 2048

// GEMM tiling
#define BM 64
#define BN 128
#define BD 16
#define PITCH 18   // smem row pitch in floats (72B) -> conflict-free strided .64 loads

// ---------------- scratch (device globals: no allocation allowed) ----------------
__device__ float g_invn[Nn];       // 1/max(||x||,1e-12)
__device__ float g_cn2[Kk];        // ||c_k||^2
__device__ int   g_idx[Nn];        // argmin indices
__device__ float g_counts[Kk];     // histogram (float, matches reference onehot sum)
__device__ float g_dw[Kk * Dd];    // scatter sum of X rows
__device__ float g_nsum;           // sum of pre-smoothed new_size

// ---------------- init: zero the accumulated buffers (replayed per graph launch) --
__global__ void k_init() {
    int i = blockIdx.x * 256 + threadIdx.x;
    if (i < Kk * Dd) g_dw[i] = 0.0f;
    if (i < Kk) g_counts[i] = 0.0f;
}

// ---------------- row norms of X (fp64 accum -> accurate fp32 reciprocal) --------
__global__ void k_rownorm(const float* __restrict__ X) {
    int gw = (blockIdx.x * blockDim.x + threadIdx.x) >> 5;
    int lane = threadIdx.x & 31;
    if (gw >= Nn) return;
    const float* row = X + (size_t)gw * Dd;
    double s = 0.0;
#pragma unroll
    for (int d = lane * 4; d < Dd; d += 128) {
        float4 v = *(const float4*)(row + d);
        s += (double)v.x * v.x + (double)v.y * v.y + (double)v.z * v.z + (double)v.w * v.w;
    }
#pragma unroll
    for (int o = 16; o; o >>= 1) s += __shfl_down_sync(0xffffffffu, s, o);
    if (lane == 0) {
        double nrm = sqrt(s);
        if (nrm < 1e-12) nrm = 1e-12;
        g_invn[gw] = (float)(1.0 / nrm);
    }
}

// ---------------- ||c_k||^2 (fp64 accum: only cross-k relative accuracy matters) -
__global__ void k_cnorm(const float* __restrict__ C) {
    int gw = (blockIdx.x * blockDim.x + threadIdx.x) >> 5;
    int lane = threadIdx.x & 31;
    if (gw >= Kk) return;
    const float* row = C + (size_t)gw * Dd;
    double s = 0.0;
#pragma unroll
    for (int d = lane * 4; d < Dd; d += 128) {
        float4 v = *(const float4*)(row + d);
        s += (double)v.x * v.x + (double)v.y * v.y + (double)v.z * v.z + (double)v.w * v.w;
    }
#pragma unroll
    for (int o = 16; o; o >>= 1) s += __shfl_down_sync(0xffffffffu, s, o);
    if (lane == 0) g_cn2[gw] = (float)s;
}

// ---------------- fused distance-GEMM + argmin --------------------------------
// One CTA = 64 rows of X, loops over all K clusters in chunks of 128.
// Per-thread micro-tile 4(M) x 8(N). Accumulators are packed f32x2 pairs over
// the D dimension (lo = even d, hi = odd d) -> fma.rn.f32x2 doubles fp32 rate
// with no pack/broadcast instructions.
__global__ __launch_bounds__(256, 2)
void k_gemm_argmin(const float* __restrict__ X, const float* __restrict__ C,
                   float* __restrict__ oIdx)
{
    __shared__ __align__(16) float As[BM * PITCH];
    __shared__ __align__(16) float Bs[BN * PITCH];
    __shared__ float sInv[BM];
    __shared__ float sMV[BM][16];
    __shared__ int   sMI[BM][16];

    const int tid = threadIdx.x;
    const int tx = tid & 15;       // N dimension (owns n = tx + 16*j)
    const int ty = tid >> 4;       // M dimension (owns m = ty*4 + i)
    const int m0 = blockIdx.x * BM;

    if (tid < BM) sInv[tid] = g_invn[m0 + tid];
    __syncthreads();

    float minv[4];
    int   mini[4];
#pragma unroll
    for (int i = 0; i < 4; ++i) { minv[i] = 3.4e38f; mini[i] = 0; }

    const int am = tid >> 2, aseg = tid & 3;   // A staging: float4 per thread
    const int bn = tid >> 1, bseg = tid & 1;   // B staging: 2 float4 per thread

    for (int nc = 0; nc < Kk / BN; ++nc) {
        unsigned long long acc[4][8];
#pragma unroll
        for (int i = 0; i < 4; ++i)
#pragma unroll
            for (int j = 0; j < 8; ++j) acc[i][j] = 0ull;

        const float* Cb = C + (size_t)(nc * BN) * Dd;

        for (int dc = 0; dc < Dd / BD; ++dc) {
            // stage A tile (normalized on the fly): 64 x 16, pitch 18
            {
                float4 av = *(const float4*)(X + (size_t)(m0 + am) * Dd + dc * BD + aseg * 4);
                float sc = sInv[am];
                av.x *= sc; av.y *= sc; av.z *= sc; av.w *= sc;
                float* ad = As + am * PITCH + aseg * 4;
                *(float2*)(ad + 0) = make_float2(av.x, av.y);
                *(float2*)(ad + 2) = make_float2(av.z, av.w);
            }
            // stage B tile: 128 x 16, pitch 18
            {
                const float4* bsrc = (const float4*)(Cb + (size_t)bn * Dd + dc * BD + bseg * 8);
                float4 b0 = bsrc[0], b1 = bsrc[1];
                float* bd = Bs + bn * PITCH + bseg * 8;
                *(float2*)(bd + 0) = make_float2(b0.x, b0.y);
                *(float2*)(bd + 2) = make_float2(b0.z, b0.w);
                *(float2*)(bd + 4) = make_float2(b1.x, b1.y);
                *(float2*)(bd + 6) = make_float2(b1.z, b1.w);
            }
            __syncthreads();

#pragma unroll
            for (int dp = 0; dp < 8; ++dp) {
                unsigned long long bfrag[8], afrag[4];
#pragma unroll
                for (int j = 0; j < 8; ++j)
                    bfrag[j] = *(const unsigned long long*)(Bs + (tx + 16 * j) * PITCH + dp * 2);
#pragma unroll
                for (int i = 0; i < 4; ++i)
                    afrag[i] = *(const unsigned long long*)(As + (ty * 4 + i) * PITCH + dp * 2);
#pragma unroll
                for (int i = 0; i < 4; ++i)
#pragma unroll
                    for (int j = 0; j < 8; ++j)
                        asm("fma.rn.f32x2 %0, %1, %2, %0;"
                            : "+l"(acc[i][j]) : "l"(afrag[i]), "l"(bfrag[j]));
            }
            __syncthreads();
        }

        // epilogue for this K chunk: score = ||c||^2 - 2*dot ; update running min
#pragma unroll
        for (int j = 0; j < 8; ++j) {
            int gn = nc * BN + tx + 16 * j;
            float cn = g_cn2[gn];
#pragma unroll
            for (int i = 0; i < 4; ++i) {
                float lo, hi;
                asm("mov.b64 {%0, %1}, %2;" : "=f"(lo), "=f"(hi) : "l"(acc[i][j]));
                float sc = cn - 2.0f * (lo + hi);
                if (sc < minv[i] || (sc == minv[i] && gn < mini[i])) {
                    minv[i] = sc; mini[i] = gn;
                }
            }
        }
    }

    // cross-thread argmin reduction per row (tie -> smallest index, like jnp.argmin)
#pragma unroll
    for (int i = 0; i < 4; ++i) {
        sMV[ty * 4 + i][tx] = minv[i];
        sMI[ty * 4 + i][tx] = mini[i];
    }
    __syncthreads();
    if (tid < BM) {
        float bv = sMV[tid][0]; int bi = sMI[tid][0];
#pragma unroll
        for (int t = 1; t < 16; ++t) {
            float v = sMV[tid][t]; int ii = sMI[tid][t];
            if (v < bv || (v == bv && ii < bi)) { bv = v; bi = ii; }
        }
        g_idx[m0 + tid] = bi;
        oIdx[m0 + tid] = (float)bi;
    }
}

// ---------------- gather quantized rows + scatter dw + histogram ----------------
__global__ void k_gather(const float* __restrict__ X, const float* __restrict__ C,
                         float* __restrict__ oQ)
{
    int n = blockIdx.x;
    int k = g_idx[n];
    int t = threadIdx.x;   // 128 threads, 4 floats each
    float4 c = *(const float4*)(C + (size_t)k * Dd + t * 4);
    *(float4*)(oQ + (size_t)n * Dd + t * 4) = c;
    float4 x = *(const float4*)(X + (size_t)n * Dd + t * 4);
    float* dw = g_dw + (size_t)k * Dd + t * 4;
    atomicAdd(dw + 0, x.x);
    atomicAdd(dw + 1, x.y);
    atomicAdd(dw + 2, x.z);
    atomicAdd(dw + 3, x.w);
    if (t == 0) atomicAdd(&g_counts[k], 1.0f);
}

// ---------------- n = sum_k (ema_size*0.99 + 0.01*count) ------------------------
__global__ void k_reduce(const float* __restrict__ ES) {
    __shared__ float sh[256];
    int tid = threadIdx.x;
    float s = 0.0f;
    for (int i = tid; i < Kk; i += 256)
        s += ES[i] * 0.99f + 0.01f * g_counts[i];
    sh[tid] = s;
    __syncthreads();
    for (int o = 128; o; o >>= 1) {
        if (tid < o) sh[tid] += sh[tid + o];
        __syncthreads();
    }
    if (tid == 0) g_nsum = sh[0];
}

// ---------------- finalize EMA outputs ------------------------------------------
__global__ void k_finalize(const float* __restrict__ ES, const float* __restrict__ EW,
                           float* __restrict__ oC, float* __restrict__ oS,
                           float* __restrict__ oW)
{
    int i = blockIdx.x * 256 + threadIdx.x;   // exactly Kk*Dd threads
    int k = i >> 9;                            // Dd = 512
    float nw  = EW[i] * 0.99f + 0.01f * g_dw[i];
    float pre = ES[k] * 0.99f + 0.01f * g_counts[k];
    float nt  = g_nsum;
    float ns  = (pre + 1e-5f) / (nt + 2048.0f * 1e-5f) * nt;
    oW[i] = nw;
    oC[i] = nw / ns;
    if ((i & 511) == 0) oS[k] = ns;
}

// ---------------- launch ---------------------------------------------------------
extern "C" void kernel_launch(void* const* d_in, const int* in_sizes, int n_in,
                              void* d_out, int out_size)
{
    const float* X  = (const float*)d_in[0];   // [N, D]
    const float* C  = (const float*)d_in[1];   // [K, D]
    const float* ES = (const float*)d_in[2];   // [K]
    const float* EW = (const float*)d_in[3];   // [K, D]

    float* out = (float*)d_out;
    float* oQ = out;                               // quantized    N*D
    float* oI = oQ + (size_t)Nn * Dd;              // indices      N
    float* oC = oI + Nn;                           // new_centroids K*D
    float* oS = oC + (size_t)Kk * Dd;              // new_size     K
    float* oW = oS + Kk;                           // new_w        K*D

    k_init<<<(Kk * Dd) / 256, 256>>>();
    k_rownorm<<<(Nn * 32) / 256, 256>>>(X);
    k_cnorm<<<(Kk * 32) / 256, 256>>>(C);
    k_gemm_argmin<<<Nn / BM, 256>>>(X, C, oI);
    k_gather<<<Nn, 128>>>(X, C, oQ);
    k_reduce<<<1, 256>>>(ES);
    k_finalize<<<(Kk * Dd) / 256, 256>>>(ES, EW, oC, oS, oW);
}

// round 16
// speedup vs baseline: 1.3513x; 1.3513x over previous
#include <cuda_runtime.h>
#include <cuda_fp16.h>
#include <cuda_pipeline.h>
#include <math.h>
#include <stdint.h>

// ---------------- problem constants ----------------
#define Nn 32768
#define Dd 512
#define Kk 2048

// ---------------- GEMM tiling ----------------
#define MT 128                 // CTA M tile (rows of X)
#define NTL 128                // CTA N tile (clusters per ntile)
#define BK 32                  // d per chunk
#define NSTAGE 4
#define APITCH 80              // bytes per smem row (40 halves): conflict-free ldmatrix
#define STB 20480              // stage bytes: A(128*80) + B(128*80)
#define DYN_SMEM (NSTAGE * STB + 2048 * 4)   // stages + cn2
#define NTILES (Kk / NTL)      // 16
#define DCHUNKS (Dd / BK)      // 16
#define GTOT (NTILES * DCHUNKS) // 256

// ---------------- device scratch (no allocation allowed) ----------------
__device__ __align__(16) __half g_xh[(size_t)Nn * Dd];   // normalized X, fp16 (32MB)
__device__ __align__(16) __half g_ch[(size_t)Kk * Dd];   // centroids, fp16 (2MB)
__device__ float g_invn[Nn];
__device__ float g_cn2[Kk];
__device__ int4  g_cand[Nn];     // top-3 candidate indices per row
__device__ int   g_idx[Nn];
__device__ int   g_cnt[Kk];
__device__ int   g_off[Kk];
__device__ int   g_cur[Kk];
__device__ int   g_list[Nn];
__device__ float g_dw[Kk * Dd];
__device__ float g_nsum;

// ---------------- helpers ----------------
__device__ __forceinline__ uint32_t smem_u32(const void* p) {
    uint32_t a;
    asm("{ .reg .u64 t; cvta.to.shared.u64 t, %1; cvt.u32.u64 %0, t; }" : "=r"(a) : "l"(p));
    return a;
}
__device__ __forceinline__ void ldmatrix_x4(uint32_t* r, uint32_t addr) {
    asm volatile("ldmatrix.sync.aligned.m8n8.x4.shared.b16 {%0,%1,%2,%3}, [%4];"
                 : "=r"(r[0]), "=r"(r[1]), "=r"(r[2]), "=r"(r[3]) : "r"(addr));
}
__device__ __forceinline__ void ldmatrix_x2(uint32_t* r, uint32_t addr) {
    asm volatile("ldmatrix.sync.aligned.m8n8.x2.shared.b16 {%0,%1}, [%2];"
                 : "=r"(r[0]), "=r"(r[1]) : "r"(addr));
}
__device__ __forceinline__ void mma16816(float* c, const uint32_t* a, const uint32_t* b) {
    asm volatile("mma.sync.aligned.m16n8k16.row.col.f32.f16.f16.f32 "
                 "{%0,%1,%2,%3}, {%4,%5,%6,%7}, {%8,%9}, {%0,%1,%2,%3};"
                 : "+f"(c[0]), "+f"(c[1]), "+f"(c[2]), "+f"(c[3])
                 : "r"(a[0]), "r"(a[1]), "r"(a[2]), "r"(a[3]), "r"(b[0]), "r"(b[1]));
}
__device__ __forceinline__ unsigned long long packkey(float s, int n) {
    unsigned u = __float_as_uint(s);
    u = (u & 0x80000000u) ? ~u : (u | 0x80000000u);   // monotone-sortable float
    return ((unsigned long long)u << 32) | (unsigned)n;
}
__device__ __forceinline__ void upd3(unsigned long long& t0, unsigned long long& t1,
                                     unsigned long long& t2, unsigned long long k) {
    if (k < t2) {
        if (k < t1) {
            t2 = t1;
            if (k < t0) { t1 = t0; t0 = k; } else { t1 = k; }
        } else { t2 = k; }
    }
}

// ---------------- init counters ----------------
__global__ void k_init() {
    int t = threadIdx.x;
    for (int j = t; j < Kk; j += 256) { g_cnt[j] = 0; g_cur[j] = 0; }
}

// ---------------- row norms of X ----------------
__global__ void k_rownorm(const float* __restrict__ X) {
    int gw = (blockIdx.x * blockDim.x + threadIdx.x) >> 5;
    int lane = threadIdx.x & 31;
    if (gw >= Nn) return;
    const float* row = X + (size_t)gw * Dd;
    double s = 0.0;
#pragma unroll
    for (int d = lane * 4; d < Dd; d += 128) {
        float4 v = *(const float4*)(row + d);
        s += (double)v.x * v.x + (double)v.y * v.y + (double)v.z * v.z + (double)v.w * v.w;
    }
#pragma unroll
    for (int o = 16; o; o >>= 1) s += __shfl_down_sync(0xffffffffu, s, o);
    if (lane == 0) {
        double nrm = sqrt(s);
        if (nrm < 1e-12) nrm = 1e-12;
        g_invn[gw] = (float)(1.0 / nrm);
    }
}

// ---------------- ||c_k||^2 ----------------
__global__ void k_cnorm(const float* __restrict__ C) {
    int gw = (blockIdx.x * blockDim.x + threadIdx.x) >> 5;
    int lane = threadIdx.x & 31;
    if (gw >= Kk) return;
    const float* row = C + (size_t)gw * Dd;
    double s = 0.0;
#pragma unroll
    for (int d = lane * 4; d < Dd; d += 128) {
        float4 v = *(const float4*)(row + d);
        s += (double)v.x * v.x + (double)v.y * v.y + (double)v.z * v.z + (double)v.w * v.w;
    }
#pragma unroll
    for (int o = 16; o; o >>= 1) s += __shfl_down_sync(0xffffffffu, s, o);
    if (lane == 0) g_cn2[gw] = (float)s;
}

// ---------------- pack normalized X -> fp16 ----------------
__global__ void k_packx(const float* __restrict__ X) {
    int i = blockIdx.x * 256 + threadIdx.x;      // Nn*Dd/4 threads
    int base = i * 4;
    float inv = g_invn[base >> 9];
    float4 v = *(const float4*)(X + base);
    __half2* dst = (__half2*)(g_xh + base);
    dst[0] = __floats2half2_rn(v.x * inv, v.y * inv);
    dst[1] = __floats2half2_rn(v.z * inv, v.w * inv);
}

// ---------------- pack C -> fp16 ----------------
__global__ void k_packc(const float* __restrict__ C) {
    int i = blockIdx.x * 256 + threadIdx.x;      // Kk*Dd/4 threads
    int base = i * 4;
    float4 v = *(const float4*)(C + base);
    __half2* dst = (__half2*)(g_ch + base);
    dst[0] = __floats2half2_rn(v.x, v.y);
    dst[1] = __floats2half2_rn(v.z, v.w);
}

// ---------------- cp.async one stage (A chunk + B chunk) ----------------
__device__ __forceinline__ void issue_stage(char* dsm, int m0, int tid, int g) {
    char* sa = dsm + (size_t)(g & (NSTAGE - 1)) * STB;
    int nt = g >> 4, dc = g & 15;
    const __half* xsrc = g_xh + (size_t)m0 * Dd + dc * BK;
    const __half* csrc = g_ch + (size_t)(nt * NTL) * Dd + dc * BK;
#pragma unroll
    for (int q = 0; q < 2; ++q) {
        int s = tid + 256 * q;                   // 0..511 A segments
        int row = s >> 2, c16 = s & 3;
        __pipeline_memcpy_async(sa + row * APITCH + c16 * 16,
                                xsrc + (size_t)row * Dd + c16 * 8, 16);
    }
#pragma unroll
    for (int q = 0; q < 2; ++q) {
        int s = tid + 256 * q;                   // 0..511 B segments
        int row = s >> 2, c16 = s & 3;
        __pipeline_memcpy_async(sa + 10240 + row * APITCH + c16 * 16,
                                csrc + (size_t)row * Dd + c16 * 8, 16);
    }
}

// ---------------- HMMA GEMM + top-3 candidate selection ----------------
// grid = 256 CTAs (one per 128-row M tile), 256 threads = 8 warps in 2(M) x 4(N).
// Warp tile 64x32. Per n-tile of 128 clusters: acc = Xn_h @ C_h^T (fp16 in, f32 acc),
// score = ||c||^2 - 2*acc, fold into per-row top-3 packed keys.
__global__ __launch_bounds__(256, 1) void k_hmma() {
    extern __shared__ char dsm[];
    float* scn = (float*)(dsm + NSTAGE * STB);   // cn2 cache (2048 f32)

    const int tid = threadIdx.x, lane = tid & 31, wid = tid >> 5;
    const int wm = wid >> 2, wn = wid & 3;
    const int m0 = blockIdx.x * MT;
    const uint32_t sbase = smem_u32(dsm);

#pragma unroll
    for (int i = 0; i < 8; ++i) scn[tid + 256 * i] = g_cn2[tid + 256 * i];

    // prologue: stages 0..2
    for (int s = 0; s < NSTAGE - 1; ++s) { issue_stage(dsm, m0, tid, s); __pipeline_commit(); }

    unsigned long long t0[8], t1[8], t2[8];
#pragma unroll
    for (int r = 0; r < 8; ++r) { t0[r] = ~0ull; t1[r] = ~0ull; t2[r] = ~0ull; }

    const int mwbase = wm * 64;
    const int nwbase = wn * 32;
    int g = 0;

    for (int nt = 0; nt < NTILES; ++nt) {
        float acc[4][4][4];
#pragma unroll
        for (int mt = 0; mt < 4; ++mt)
#pragma unroll
            for (int nb = 0; nb < 4; ++nb)
#pragma unroll
                for (int e = 0; e < 4; ++e) acc[mt][nb][e] = 0.0f;

        for (int dc = 0; dc < DCHUNKS; ++dc, ++g) {
            __pipeline_wait_prior(2);
            __syncthreads();
            if (g + NSTAGE - 1 < GTOT) issue_stage(dsm, m0, tid, g + NSTAGE - 1);
            __pipeline_commit();     // commit every iter (possibly empty) -> uniform accounting

            uint32_t uA = sbase + (uint32_t)(g & (NSTAGE - 1)) * STB;
            uint32_t uB = uA + 10240;
#pragma unroll
            for (int k16 = 0; k16 < 2; ++k16) {
                uint32_t afr[4][4], bfr[4][2];
#pragma unroll
                for (int mt = 0; mt < 4; ++mt) {
                    uint32_t addr = uA + (mwbase + mt * 16 + (lane & 15)) * APITCH
                                       + (k16 * 16 + (lane >> 4) * 8) * 2;
                    ldmatrix_x4(afr[mt], addr);
                }
                int l = lane & 15;
#pragma unroll
                for (int nb = 0; nb < 4; ++nb) {
                    uint32_t addr = uB + (nwbase + nb * 8 + (l & 7)) * APITCH
                                       + (k16 * 16 + ((l >> 3) & 1) * 8) * 2;
                    ldmatrix_x2(bfr[nb], addr);
                }
#pragma unroll
                for (int mt = 0; mt < 4; ++mt)
#pragma unroll
                    for (int nb = 0; nb < 4; ++nb)
                        mma16816(acc[mt][nb], afr[mt], bfr[nb]);
            }
        }

        // fold scores into per-row top-3
#pragma unroll
        for (int mt = 0; mt < 4; ++mt) {
#pragma unroll
            for (int nb = 0; nb < 4; ++nb) {
                int n0 = nt * NTL + nwbase + nb * 8 + 2 * (lane & 3);
                float cnA = scn[n0], cnB = scn[n0 + 1];
                upd3(t0[mt * 2],     t1[mt * 2],     t2[mt * 2],
                     packkey(cnA - 2.0f * acc[mt][nb][0], n0));
                upd3(t0[mt * 2],     t1[mt * 2],     t2[mt * 2],
                     packkey(cnB - 2.0f * acc[mt][nb][1], n0 + 1));
                upd3(t0[mt * 2 + 1], t1[mt * 2 + 1], t2[mt * 2 + 1],
                     packkey(cnA - 2.0f * acc[mt][nb][2], n0));
                upd3(t0[mt * 2 + 1], t1[mt * 2 + 1], t2[mt * 2 + 1],
                     packkey(cnB - 2.0f * acc[mt][nb][3], n0 + 1));
            }
        }
    }

    __pipeline_wait_prior(0);
    __syncthreads();

    // merge: 16 participants per row (4 n-warps x 4 lane-quads), 3 keys each
    unsigned long long* mk = (unsigned long long*)dsm;   // 128*16*3*8 = 49KB, aliases stages
#pragma unroll
    for (int rs = 0; rs < 8; ++rs) {
        int ml = wm * 64 + (rs >> 1) * 16 + (rs & 1) * 8 + (lane >> 2);
        int p = wn * 4 + (lane & 3);
        unsigned long long* d = mk + (size_t)(ml * 16 + p) * 3;
        d[0] = t0[rs]; d[1] = t1[rs]; d[2] = t2[rs];
    }
    __syncthreads();
    if (tid < MT) {
        unsigned long long a = ~0ull, b = ~0ull, c = ~0ull;
        const unsigned long long* s = mk + (size_t)tid * 48;
        for (int j = 0; j < 48; ++j) upd3(a, b, c, s[j]);
        g_cand[m0 + tid] = make_int4((int)(unsigned)a, (int)(unsigned)b, (int)(unsigned)c, 0);
    }
}

// ---------------- exact fp32 refine over 3 candidates ----------------
__global__ void k_refine(const float* __restrict__ X, const float* __restrict__ C,
                         float* __restrict__ oIdx) {
    int wid = threadIdx.x >> 5, lane = threadIdx.x & 31;
    int row = blockIdx.x * 8 + wid;
    int4 cd = g_cand[row];
    const float4* xr = (const float4*)(X + (size_t)row * Dd);
    const float4* c0 = (const float4*)(C + (size_t)cd.x * Dd);
    const float4* c1 = (const float4*)(C + (size_t)cd.y * Dd);
    const float4* c2 = (const float4*)(C + (size_t)cd.z * Dd);
    float s0 = 0.f, s1 = 0.f, s2 = 0.f;
#pragma unroll
    for (int e = lane; e < Dd / 4; e += 32) {
        float4 x = xr[e];
        float4 a = c0[e], b = c1[e], c = c2[e];
        s0 = fmaf(x.x, a.x, fmaf(x.y, a.y, fmaf(x.z, a.z, fmaf(x.w, a.w, s0))));
        s1 = fmaf(x.x, b.x, fmaf(x.y, b.y, fmaf(x.z, b.z, fmaf(x.w, b.w, s1))));
        s2 = fmaf(x.x, c.x, fmaf(x.y, c.y, fmaf(x.z, c.z, fmaf(x.w, c.w, s2))));
    }
#pragma unroll
    for (int o = 16; o; o >>= 1) {
        s0 += __shfl_down_sync(0xffffffffu, s0, o);
        s1 += __shfl_down_sync(0xffffffffu, s1, o);
        s2 += __shfl_down_sync(0xffffffffu, s2, o);
    }
    if (lane == 0) {
        float inv = g_invn[row];
        float d0 = g_cn2[cd.x] - 2.0f * inv * s0;
        float d1 = g_cn2[cd.y] - 2.0f * inv * s1;
        float d2 = g_cn2[cd.z] - 2.0f * inv * s2;
        float bv = d0; int bi = cd.x;
        if (d1 < bv || (d1 == bv && cd.y < bi)) { bv = d1; bi = cd.y; }
        if (d2 < bv || (d2 == bv && cd.z < bi)) { bv = d2; bi = cd.z; }
        g_idx[row] = bi;
        oIdx[row] = (float)bi;
    }
}

// ---------------- histogram / scan / fill / per-cluster reduce ----------------
__global__ void k_hist() {
    int i = blockIdx.x * 256 + threadIdx.x;
    if (i < Nn) atomicAdd(&g_cnt[g_idx[i]], 1);
}
__global__ void k_scan() {
    __shared__ int part[256];
    int t = threadIdx.x;
    int loc[8];
    int sum = 0;
#pragma unroll
    for (int i = 0; i < 8; ++i) {
        int c = g_cnt[t * 8 + i];
        loc[i] = sum; sum += c;
    }
    part[t] = sum;
    __syncthreads();
    int total = sum;
    for (int o = 1; o < 256; o <<= 1) {
        int v = (t >= o) ? part[t - o] : 0;
        __syncthreads();
        part[t] += v;
        __syncthreads();
    }
    int excl = part[t] - total;
#pragma unroll
    for (int i = 0; i < 8; ++i) g_off[t * 8 + i] = excl + loc[i];
}
__global__ void k_fill() {
    int i = blockIdx.x * 256 + threadIdx.x;
    if (i < Nn) {
        int k = g_idx[i];
        int pos = atomicAdd(&g_cur[k], 1);
        g_list[g_off[k] + pos] = i;
    }
}
__global__ void k_dw(const float* __restrict__ X) {
    int k = blockIdx.x;
    int cnt = g_cnt[k], off = g_off[k];
    int t = threadIdx.x;                 // 256 threads, 2 floats each
    float2 acc = make_float2(0.f, 0.f);
    for (int j = 0; j < cnt; ++j) {
        int row = g_list[off + j];
        float2 v = ((const float2*)(X + (size_t)row * Dd))[t];
        acc.x += v.x; acc.y += v.y;
    }
    ((float2*)(g_dw + (size_t)k * Dd))[t] = acc;
}
__global__ void k_quant(const float* __restrict__ C, float* __restrict__ oQ) {
    int n = blockIdx.x;
    int k = g_idx[n];
    int t = threadIdx.x;                 // 128 threads x float4
    float4 c = *(const float4*)(C + (size_t)k * Dd + t * 4);
    *(float4*)(oQ + (size_t)n * Dd + t * 4) = c;
}

// ---------------- n = sum_k (ema_size*0.99 + 0.01*count) ----------------
__global__ void k_reduce(const float* __restrict__ ES) {
    __shared__ float sh[256];
    int tid = threadIdx.x;
    float s = 0.0f;
    for (int i = tid; i < Kk; i += 256)
        s += ES[i] * 0.99f + 0.01f * (float)g_cnt[i];
    sh[tid] = s;
    __syncthreads();
    for (int o = 128; o; o >>= 1) {
        if (tid < o) sh[tid] += sh[tid + o];
        __syncthreads();
    }
    if (tid == 0) g_nsum = sh[0];
}

// ---------------- finalize EMA outputs ----------------
__global__ void k_finalize(const float* __restrict__ ES, const float* __restrict__ EW,
                           float* __restrict__ oC, float* __restrict__ oS,
                           float* __restrict__ oW)
{
    int i = blockIdx.x * 256 + threadIdx.x;
    int k = i >> 9;
    float nw  = EW[i] * 0.99f + 0.01f * g_dw[i];
    float pre = ES[k] * 0.99f + 0.01f * (float)g_cnt[k];
    float nt  = g_nsum;
    float ns  = (pre + 1e-5f) / (nt + 2048.0f * 1e-5f) * nt;
    oW[i] = nw;
    oC[i] = nw / ns;
    if ((i & 511) == 0) oS[k] = ns;
}

// ---------------- launch ----------------
extern "C" void kernel_launch(void* const* d_in, const int* in_sizes, int n_in,
                              void* d_out, int out_size)
{
    const float* X  = (const float*)d_in[0];   // [N, D]
    const float* C  = (const float*)d_in[1];   // [K, D]
    const float* ES = (const float*)d_in[2];   // [K]
    const float* EW = (const float*)d_in[3];   // [K, D]

    float* out = (float*)d_out;
    float* oQ = out;                               // quantized     N*D
    float* oI = oQ + (size_t)Nn * Dd;              // indices       N
    float* oC = oI + Nn;                           // new_centroids K*D
    float* oS = oC + (size_t)Kk * Dd;              // new_size      K
    float* oW = oS + Kk;                           // new_w         K*D

    cudaFuncSetAttribute(k_hmma, cudaFuncAttributeMaxDynamicSharedMemorySize, DYN_SMEM);

    k_init<<<1, 256>>>();
    k_rownorm<<<(Nn * 32) / 256, 256>>>(X);
    k_cnorm<<<(Kk * 32) / 256, 256>>>(C);
    k_packx<<<(Nn * Dd / 4) / 256, 256>>>(X);
    k_packc<<<(Kk * Dd / 4) / 256, 256>>>(C);
    k_hmma<<<Nn / MT, 256, DYN_SMEM>>>();
    k_refine<<<Nn / 8, 256>>>(X, C, oI);
    k_hist<<<Nn / 256, 256>>>();
    k_scan<<<1, 256>>>();
    k_fill<<<Nn / 256, 256>>>();
    k_dw<<<Kk, 256>>>(X);
    k_quant<<<Nn, 128>>>(C, oQ);
    k_reduce<<<1, 256>>>(ES);
    k_finalize<<<(Kk * Dd) / 256, 256>>>(ES, EW, oC, oS, oW);
}